// round 6
// baseline (speedup 1.0000x reference)
#include <cuda_runtime.h>
#include <cuda_fp16.h>
#include <cstdint>
#include <math.h>

#define N_ITEMS 8192
#define DIM     64
#define BATCHSZ 4096
#define LN2F    0.69314718055994531f
#define ITLG2E  20.609947181438156f   /* (1/0.07) * log2(e) */
#define NCH     32

// ---------------- device scratch (no allocations allowed) ----------------
__device__ uint32_t g_fh[N_ITEMS * 32];   // normalized rows, half2-packed [row][32]
__device__ float    g_Z[2 * N_ITEMS];
__device__ float    g_P[2 * N_ITEMS];     // log2-domain positive-logit sums
__device__ float    g_C[2 * N_ITEMS];

// ---------------- helpers --------------------------------------------------
static __device__ __forceinline__ uint32_t smem_u32(const void* p) {
    uint32_t a;
    asm("{ .reg .u64 t; cvta.to.shared.u64 t, %1; cvt.u32.u64 %0, t; }" : "=r"(a) : "l"(p));
    return a;
}
static __device__ __forceinline__ float ex2f(float x) {
    float y; asm("ex2.approx.ftz.f32 %0, %1;" : "=f"(y) : "f"(x)); return y;
}
static __device__ __forceinline__ float lg2f(float x) {
    float y; asm("lg2.approx.ftz.f32 %0, %1;" : "=f"(y) : "f"(x)); return y;
}
static __device__ __forceinline__ void cp16(uint32_t dst, const void* src) {
    asm volatile("cp.async.cg.shared.global [%0], [%1], 16;" :: "r"(dst), "l"(src));
}
#define CP_COMMIT() asm volatile("cp.async.commit_group;" ::: "memory")
static __device__ __forceinline__ void ldsm4(uint32_t* r, uint32_t addr) {
    asm volatile("ldmatrix.sync.aligned.m8n8.x4.shared.b16 {%0,%1,%2,%3}, [%4];"
                 : "=r"(r[0]), "=r"(r[1]), "=r"(r[2]), "=r"(r[3]) : "r"(addr));
}
static __device__ __forceinline__ void mma16816(float* d, const uint32_t* a,
                                                uint32_t b0, uint32_t b1) {
    asm volatile("mma.sync.aligned.m16n8k16.row.col.f32.f16.f16.f32 "
                 "{%0,%1,%2,%3}, {%4,%5,%6,%7}, {%8,%9}, {%0,%1,%2,%3};"
                 : "+f"(d[0]), "+f"(d[1]), "+f"(d[2]), "+f"(d[3])
                 : "r"(a[0]), "r"(a[1]), "r"(a[2]), "r"(a[3]), "r"(b0), "r"(b1));
}

// ---------------- kernel 1: fused normalize (fp16) + rating ---------------
__global__ __launch_bounds__(256) void prep_kernel(const float* __restrict__ emb,
                                                   const int* __restrict__ idx,
                                                   const float* __restrict__ w,
                                                   const float* __restrict__ bias,
                                                   float* __restrict__ out) {
    int bid  = blockIdx.x;
    int wid  = threadIdx.x >> 5;
    int lane = threadIdx.x & 31;
    if (bid < N_ITEMS / 8) {
        int row = bid * 8 + wid;
        float2 v = reinterpret_cast<const float2*>(emb + (size_t)row * DIM)[lane];
        float ss = v.x * v.x + v.y * v.y;
        #pragma unroll
        for (int o = 16; o; o >>= 1) ss += __shfl_xor_sync(0xFFFFFFFFu, ss, o);
        float inv = 1.0f / fmaxf(sqrtf(ss), 1e-12f);
        __half2 h = __floats2half2_rn(v.x * inv, v.y * inv);
        g_fh[row * 32 + lane] = *reinterpret_cast<uint32_t*>(&h);
    } else {
        int r = (bid - N_ITEMS / 8) * 8 + wid;
        int it = idx[r];
        float2 v  = reinterpret_cast<const float2*>(emb + (size_t)it * DIM)[lane];
        float2 ww = reinterpret_cast<const float2*>(w)[lane];
        float s = v.x * ww.x + v.y * ww.y;
        #pragma unroll
        for (int o = 16; o; o >>= 1) s += __shfl_xor_sync(0xFFFFFFFFu, s, o);
        if (lane == 0) out[r] = 1.0f / (1.0f + __expf(-(s + bias[0])));
    }
}

// ---------------- kernel 2: fp16 HMMA SupCon --------------------------------
// grid (64,2), 256 thr. CTA: 128 rows x 4096 cols, 32 chunks of 128 cols.
// smem: A[0,16K), B ring 4 x 16K at 16K. Swizzle: 16B chunk c of row r at c^(r&7).
static __device__ __forceinline__ void load_128x128(uint32_t sdst, const char* gsrc, int tid) {
    #pragma unroll
    for (int i = tid; i < 1024; i += 256) {
        uint32_t off = ((i >> 3) * 128) + ((i & 7) * 16);
        uint32_t sw  = off ^ ((off >> 3) & 0x70);
        cp16(sdst + sw, gsrc + off);
    }
}

__global__ __launch_bounds__(256, 1) void supcon_kernel(const int* __restrict__ labels) {
    extern __shared__ char dyn[];
    __shared__ int sLab[4][128];

    const int tid  = threadIdx.x;
    const int w    = tid >> 5;
    const int lane = tid & 31;
    const int R0   = blockIdx.x * 128;
    const int C0   = blockIdx.y * 4096;
    const uint32_t sbase = smem_u32(dyn);
    const uint32_t slabA = smem_u32(&sLab[0][0]);

    // ---- prologue: A tile + chunks 0..3 (4 commit groups) ----
    load_128x128(sbase, (const char*)g_fh + (size_t)R0 * 128, tid);
    #pragma unroll
    for (int pf = 0; pf < 4; pf++) {
        uint32_t bd = sbase + 16384 + (uint32_t)pf * 16384;
        load_128x128(bd, (const char*)g_fh + (size_t)(C0 + pf * 128) * 128, tid);
        if (tid < 32) cp16(slabA + pf * 512 + tid * 16,
                           (const char*)(labels + C0 + pf * 128) + tid * 16);
        CP_COMMIT();
    }
    asm volatile("cp.async.wait_group 3;" ::: "memory");
    __syncthreads();

    // ---- A fragments (chunk-invariant): rows w*16..w*16+15, K=64 ----
    uint32_t ah[4][4];
    {
        int arow = w * 16 + (lane & 15);
        uint32_t rbase = sbase + (uint32_t)arow * 128;
        #pragma unroll
        for (int ks = 0; ks < 4; ks++) {
            uint32_t c = (uint32_t)(ks * 2 + (lane >> 4));
            ldsm4(ah[ks], rbase + ((c ^ (arow & 7)) << 4));
        }
    }

    // per-thread rows: grow0 = w*16 + lane/4, grow1 = +8; negM = -1/T (log2 dom)
    const int grow0 = R0 + w * 16 + (lane >> 2);
    const int grow1 = grow0 + 8;
    const float negM = -ITLG2E;
    const int rlab0 = labels[grow0];
    const int rlab1 = labels[grow1];
    const int lb = 2 * (lane & 3);
    float Z0 = 0.f, P0 = 0.f, C0c = 0.f, Z1 = 0.f, P1 = 0.f, C1c = 0.f;

    // B ldsm4 lane roles: n = ntp*16 + ((lane>>4)*8) + (lane&7), k-half = (lane>>3)&1
    const int bnoff = (((lane >> 4) & 1) << 3) + (lane & 7);
    const uint32_t bksel = (uint32_t)((lane >> 3) & 1);

    for (int t = 0; t < NCH; t++) {
        if (t > 0) {
            asm volatile("cp.async.wait_group 3;" ::: "memory");
            __syncthreads();
        }
        const int buf = t & 3;
        const uint32_t Bb = sbase + 16384 + (uint32_t)buf * 16384;

        float acc[16][4];
        #pragma unroll
        for (int nt = 0; nt < 16; nt++)
            #pragma unroll
            for (int i = 0; i < 4; i++) acc[nt][i] = 0.f;

        #pragma unroll
        for (int ntp = 0; ntp < 8; ntp++) {
            int n = ntp * 16 + bnoff;
            uint32_t nb = Bb + (uint32_t)n * 128;
            #pragma unroll
            for (int ks = 0; ks < 4; ks++) {
                uint32_t c = (uint32_t)(ks * 2) + bksel;
                uint32_t bb[4];
                ldsm4(bb, nb + ((c ^ (n & 7)) << 4));
                mma16816(acc[2 * ntp],     ah[ks], bb[0], bb[1]);
                mma16816(acc[2 * ntp + 1], ah[ks], bb[2], bb[3]);
            }
        }

        // ---- epilogue: rows grow0/grow1, cols nt*8 + lb + {0,1} ----
        #pragma unroll
        for (int nt = 0; nt < 16; nt++) {
            int jl0 = sLab[buf][nt * 8 + lb];
            int jl1 = sLab[buf][nt * 8 + lb + 1];
            {
                float l2 = fmaf(acc[nt][0], ITLG2E, negM);
                Z0 += ex2f(l2);
                if (jl0 == rlab0) { P0 += l2; C0c += 1.f; }
            }
            {
                float l2 = fmaf(acc[nt][1], ITLG2E, negM);
                Z0 += ex2f(l2);
                if (jl1 == rlab0) { P0 += l2; C0c += 1.f; }
            }
            {
                float l2 = fmaf(acc[nt][2], ITLG2E, negM);
                Z1 += ex2f(l2);
                if (jl0 == rlab1) { P1 += l2; C1c += 1.f; }
            }
            {
                float l2 = fmaf(acc[nt][3], ITLG2E, negM);
                Z1 += ex2f(l2);
                if (jl1 == rlab1) { P1 += l2; C1c += 1.f; }
            }
        }

        // ---- diagonal fixup (once per chunk, at most one element per row) ----
        {
            int d0 = grow0 - (C0 + t * 128);
            if ((unsigned)d0 < 128u && (d0 & 6) == lb) {
                float l2 = fmaf(acc[d0 >> 3][d0 & 1], ITLG2E, negM);
                Z0 -= ex2f(l2); P0 -= l2; C0c -= 1.f;
            }
            int d1 = grow1 - (C0 + t * 128);
            if ((unsigned)d1 < 128u && (d1 & 6) == lb) {
                float l2 = fmaf(acc[d1 >> 3][2 + (d1 & 1)], ITLG2E, negM);
                Z1 -= ex2f(l2); P1 -= l2; C1c -= 1.f;
            }
        }

        __syncthreads();   // everyone done with buf t & its labels
        {
            int pc = (t + 4) & 31;
            load_128x128(Bb, (const char*)g_fh + (size_t)(C0 + pc * 128) * 128, tid);
            if (tid < 32) cp16(slabA + buf * 512 + tid * 16,
                               (const char*)(labels + C0 + pc * 128) + tid * 16);
            CP_COMMIT();
        }
    }

    // reduce across the quad (lanes sharing a row differ in lane&3)
    #pragma unroll
    for (int o = 1; o <= 2; o <<= 1) {
        Z0 += __shfl_xor_sync(0xFFFFFFFFu, Z0, o);
        P0 += __shfl_xor_sync(0xFFFFFFFFu, P0, o);
        C0c += __shfl_xor_sync(0xFFFFFFFFu, C0c, o);
        Z1 += __shfl_xor_sync(0xFFFFFFFFu, Z1, o);
        P1 += __shfl_xor_sync(0xFFFFFFFFu, P1, o);
        C1c += __shfl_xor_sync(0xFFFFFFFFu, C1c, o);
    }
    if ((lane & 3) == 0) {
        int gi = blockIdx.y * N_ITEMS + grow0;
        g_Z[gi] = Z0; g_P[gi] = P0; g_C[gi] = C0c;
        g_Z[gi + 8] = Z1; g_P[gi + 8] = P1; g_C[gi + 8] = C1c;
    }
}

// ---------------- kernel 3: finalize loss ---------------------------------
__global__ __launch_bounds__(1024) void finalize_kernel(float* __restrict__ out, int out_size) {
    __shared__ float s[1024];
    int tid = threadIdx.x;
    float acc = 0.f;
    #pragma unroll
    for (int k = 0; k < 8; k++) {
        int r = tid + k * 1024;
        float Zv = g_Z[r] + g_Z[N_ITEMS + r];
        float Pv = (g_P[r] + g_P[N_ITEMS + r]) * LN2F;   // log2 -> ln
        float Cv = g_C[r] + g_C[N_ITEMS + r];
        float lnZ = lg2f(Zv + 1e-6f) * LN2F;
        acc += (Pv - Cv * lnZ) / (Cv + 1e-6f);
    }
    s[tid] = acc;
    __syncthreads();
    for (int o = 512; o; o >>= 1) {
        if (tid < o) s[tid] += s[tid + o];
        __syncthreads();
    }
    if (tid == 0) {
        float loss = -(s[0] / (float)N_ITEMS);
        for (int i = BATCHSZ; i < out_size; i++) out[i] = loss;
    }
}

// ---------------- launch ----------------------------------------------------
extern "C" void kernel_launch(void* const* d_in, const int* in_sizes, int n_in,
                              void* d_out, int out_size) {
    const int*   idx    = (const int*)d_in[0];
    const int*   labels = (const int*)d_in[1];
    const float* emb    = (const float*)d_in[2];
    const float* w      = (const float*)d_in[3];
    const float* b      = (const float*)d_in[4];
    float* out = (float*)d_out;

    const int SMEM = 16384 + 4 * 16384;   // 81920 B
    cudaFuncSetAttribute(supcon_kernel, cudaFuncAttributeMaxDynamicSharedMemorySize, SMEM);

    prep_kernel<<<N_ITEMS / 8 + BATCHSZ / 8, 256>>>(emb, idx, w, b, out);
    supcon_kernel<<<dim3(64, 2, 1), 256, SMEM>>>(labels);
    finalize_kernel<<<1, 1024>>>(out, out_size);
}

// round 7
// speedup vs baseline: 1.7999x; 1.7999x over previous
#include <cuda_runtime.h>
#include <cuda_fp16.h>
#include <cstdint>
#include <math.h>

#define N_ITEMS 8192
#define DIM     64
#define BATCHSZ 4096
#define LN2F    0.69314718055994531f
#define ITLG2E  20.609947181438156f   /* (1/0.07) * log2(e) */
#define NCH     32

// ---------------- device scratch (no allocations allowed) ----------------
__device__ uint32_t g_fh[N_ITEMS * 32];   // normalized rows, half2-packed [row][32]
__device__ float    g_Z[2 * N_ITEMS];
__device__ float    g_P[2 * N_ITEMS];     // log2-domain positive-logit sums
__device__ float    g_C[2 * N_ITEMS];

// ---------------- helpers --------------------------------------------------
static __device__ __forceinline__ uint32_t smem_u32(const void* p) {
    uint32_t a;
    asm("{ .reg .u64 t; cvta.to.shared.u64 t, %1; cvt.u32.u64 %0, t; }" : "=r"(a) : "l"(p));
    return a;
}
static __device__ __forceinline__ float ex2f(float x) {
    float y; asm("ex2.approx.ftz.f32 %0, %1;" : "=f"(y) : "f"(x)); return y;
}
static __device__ __forceinline__ float lg2f(float x) {
    float y; asm("lg2.approx.ftz.f32 %0, %1;" : "=f"(y) : "f"(x)); return y;
}
static __device__ __forceinline__ void cp16(uint32_t dst, const void* src) {
    asm volatile("cp.async.cg.shared.global [%0], [%1], 16;" :: "r"(dst), "l"(src));
}
#define CP_COMMIT() asm volatile("cp.async.commit_group;" ::: "memory")
static __device__ __forceinline__ void ldsm4(uint32_t* r, uint32_t addr) {
    asm volatile("ldmatrix.sync.aligned.m8n8.x4.shared.b16 {%0,%1,%2,%3}, [%4];"
                 : "=r"(r[0]), "=r"(r[1]), "=r"(r[2]), "=r"(r[3]) : "r"(addr));
}
static __device__ __forceinline__ void mma16816(float* d, const uint32_t* a,
                                                uint32_t b0, uint32_t b1) {
    asm volatile("mma.sync.aligned.m16n8k16.row.col.f32.f16.f16.f32 "
                 "{%0,%1,%2,%3}, {%4,%5,%6,%7}, {%8,%9}, {%0,%1,%2,%3};"
                 : "+f"(d[0]), "+f"(d[1]), "+f"(d[2]), "+f"(d[3])
                 : "r"(a[0]), "r"(a[1]), "r"(a[2]), "r"(a[3]), "r"(b0), "r"(b1));
}

// ---------------- kernel 1: fused normalize (fp16) + rating ---------------
__global__ __launch_bounds__(256) void prep_kernel(const float* __restrict__ emb,
                                                   const int* __restrict__ idx,
                                                   const float* __restrict__ w,
                                                   const float* __restrict__ bias,
                                                   float* __restrict__ out) {
    int bid  = blockIdx.x;
    int wid  = threadIdx.x >> 5;
    int lane = threadIdx.x & 31;
    if (bid < N_ITEMS / 8) {
        int row = bid * 8 + wid;
        float2 v = reinterpret_cast<const float2*>(emb + (size_t)row * DIM)[lane];
        float ss = v.x * v.x + v.y * v.y;
        #pragma unroll
        for (int o = 16; o; o >>= 1) ss += __shfl_xor_sync(0xFFFFFFFFu, ss, o);
        float inv = 1.0f / fmaxf(sqrtf(ss), 1e-12f);
        __half2 h = __floats2half2_rn(v.x * inv, v.y * inv);
        g_fh[row * 32 + lane] = *reinterpret_cast<uint32_t*>(&h);
    } else {
        int r = (bid - N_ITEMS / 8) * 8 + wid;
        int it = idx[r];
        float2 v  = reinterpret_cast<const float2*>(emb + (size_t)it * DIM)[lane];
        float2 ww = reinterpret_cast<const float2*>(w)[lane];
        float s = v.x * ww.x + v.y * ww.y;
        #pragma unroll
        for (int o = 16; o; o >>= 1) s += __shfl_xor_sync(0xFFFFFFFFu, s, o);
        if (lane == 0) out[r] = 1.0f / (1.0f + __expf(-(s + bias[0])));
    }
}

// ---------------- kernel 2: fp16 HMMA SupCon --------------------------------
// grid (64,2), 512 thr (16 warps). CTA: 128 rows x 4096 cols, 32 chunks of 128.
// Warp (wr=w&7, wc=w>>3): rows wr*16..+15, cols wc*64..+63 of the chunk.
// smem: A[0,16K), B ring 5 x 16K at 16K, labels ring 5 x 512B at 96K+16K.
// Swizzle: 16B chunk c of row r stored at c ^ (r&7).
#define BOFF 16384
#define LOFF (16384 + 5 * 16384)
static __device__ __forceinline__ void load_128x128(uint32_t sdst, const char* gsrc, int tid) {
    #pragma unroll
    for (int i = tid; i < 1024; i += 512) {
        uint32_t off = ((i >> 3) * 128) + ((i & 7) * 16);
        uint32_t sw  = off ^ ((off >> 3) & 0x70);
        cp16(sdst + sw, gsrc + off);
    }
}

__global__ __launch_bounds__(512, 1) void supcon_kernel(const int* __restrict__ labels) {
    extern __shared__ char dyn[];
    __shared__ float sZr[256], sPr[256], sCr[256];

    const int tid  = threadIdx.x;
    const int w    = tid >> 5;
    const int lane = tid & 31;
    const int wr   = w & 7;
    const int wc   = w >> 3;
    const int R0   = blockIdx.x * 128;
    const int Cb   = blockIdx.y * 4096;
    const uint32_t sbase = smem_u32(dyn);

    // ---- prologue: group0 = {A, B0, L0}; groups 1..3 = {Bk, Lk} ----
    load_128x128(sbase, (const char*)g_fh + (size_t)R0 * 128, tid);
    #pragma unroll
    for (int pf = 0; pf < 4; pf++) {
        load_128x128(sbase + BOFF + (uint32_t)pf * 16384,
                     (const char*)g_fh + (size_t)(Cb + pf * 128) * 128, tid);
        if (tid < 32) cp16(sbase + LOFF + pf * 512 + tid * 16,
                           (const char*)(labels + Cb + pf * 128) + tid * 16);
        CP_COMMIT();
    }
    asm volatile("cp.async.wait_group 3;" ::: "memory");
    __syncthreads();

    // ---- A fragments (chunk-invariant): rows wr*16..+15, K=64 ----
    uint32_t ah[4][4];
    {
        int arow = wr * 16 + (lane & 15);
        uint32_t rbase = sbase + (uint32_t)arow * 128;
        #pragma unroll
        for (int ks = 0; ks < 4; ks++) {
            uint32_t c = (uint32_t)(ks * 2 + (lane >> 4));
            ldsm4(ah[ks], rbase + ((c ^ (arow & 7)) << 4));
        }
    }

    const int grow0 = R0 + wr * 16 + (lane >> 2);
    const int grow1 = grow0 + 8;
    const float negM = -ITLG2E;
    const int rlab0 = labels[grow0];
    const int rlab1 = labels[grow1];
    const int lb = 2 * (lane & 3);
    const int bnoff = (((lane >> 4) & 1) << 3) + (lane & 7);
    const uint32_t bksel = (uint32_t)((lane >> 3) & 1);
    float Z0 = 0.f, P0 = 0.f, C0c = 0.f, Z1 = 0.f, P1 = 0.f, C1c = 0.f;

    int buf = 0;
    for (int t = 0; t < NCH; t++) {
        if (t > 0) {
            asm volatile("cp.async.wait_group 3;" ::: "memory");
            __syncthreads();     // chunk t ready; all warps done with chunk t-1
        }
        // prefetch chunk t+4 (wraps at tail; redundant loads harmless)
        {
            int pb = buf + 4; if (pb >= 5) pb -= 5;
            int pc = (t + 4) & 31;
            load_128x128(sbase + BOFF + (uint32_t)pb * 16384,
                         (const char*)g_fh + (size_t)(Cb + pc * 128) * 128, tid);
            if (tid < 32) cp16(sbase + LOFF + pb * 512 + tid * 16,
                               (const char*)(labels + Cb + pc * 128) + tid * 16);
            CP_COMMIT();
        }
        const uint32_t Bb = sbase + BOFF + (uint32_t)buf * 16384;
        const int2* labp = reinterpret_cast<const int2*>(dyn + LOFF + buf * 512);
        const int colbase = Cb + t * 128 + wc * 64;

        #pragma unroll
        for (int ntp = 0; ntp < 4; ntp++) {
            float a0[4] = {0.f, 0.f, 0.f, 0.f};
            float a1[4] = {0.f, 0.f, 0.f, 0.f};
            int n = wc * 64 + ntp * 16 + bnoff;
            uint32_t nb = Bb + (uint32_t)n * 128;
            #pragma unroll
            for (int ks = 0; ks < 4; ks++) {
                uint32_t c = (uint32_t)(ks * 2) + bksel;
                uint32_t bb[4];
                ldsm4(bb, nb + ((c ^ (n & 7)) << 4));
                mma16816(a0, ah[ks], bb[0], bb[1]);
                mma16816(a1, ah[ks], bb[2], bb[3]);
            }

            // epilogue for these 2 n-tiles (8 values)
            int2 jA = labp[wc * 32 + ntp * 8 + (lane & 3)];
            int2 jB = labp[wc * 32 + ntp * 8 + 4 + (lane & 3)];
            {
                float l2 = fmaf(a0[0], ITLG2E, negM);
                Z0 += ex2f(l2); if (jA.x == rlab0) { P0 += l2; C0c += 1.f; }
            }
            {
                float l2 = fmaf(a0[1], ITLG2E, negM);
                Z0 += ex2f(l2); if (jA.y == rlab0) { P0 += l2; C0c += 1.f; }
            }
            {
                float l2 = fmaf(a0[2], ITLG2E, negM);
                Z1 += ex2f(l2); if (jA.x == rlab1) { P1 += l2; C1c += 1.f; }
            }
            {
                float l2 = fmaf(a0[3], ITLG2E, negM);
                Z1 += ex2f(l2); if (jA.y == rlab1) { P1 += l2; C1c += 1.f; }
            }
            {
                float l2 = fmaf(a1[0], ITLG2E, negM);
                Z0 += ex2f(l2); if (jB.x == rlab0) { P0 += l2; C0c += 1.f; }
            }
            {
                float l2 = fmaf(a1[1], ITLG2E, negM);
                Z0 += ex2f(l2); if (jB.y == rlab0) { P0 += l2; C0c += 1.f; }
            }
            {
                float l2 = fmaf(a1[2], ITLG2E, negM);
                Z1 += ex2f(l2); if (jB.x == rlab1) { P1 += l2; C1c += 1.f; }
            }
            {
                float l2 = fmaf(a1[3], ITLG2E, negM);
                Z1 += ex2f(l2); if (jB.y == rlab1) { P1 += l2; C1c += 1.f; }
            }

            // diagonal fixup (warp-uniform guard, taken in at most one chunk/ntp)
            int dbase = (R0 + wr * 16) - (colbase + ntp * 16);
            if ((unsigned)(dbase + 15) < 31u) {
                int dl0 = dbase + (lane >> 2);
                if ((unsigned)dl0 < 16u && (dl0 & 6) == lb) {
                    float v = (dl0 < 8) ? ((dl0 & 1) ? a0[1] : a0[0])
                                        : ((dl0 & 1) ? a1[1] : a1[0]);
                    float l2 = fmaf(v, ITLG2E, negM);
                    Z0 -= ex2f(l2); P0 -= l2; C0c -= 1.f;
                }
                int dl1 = dbase + 8 + (lane >> 2);
                if ((unsigned)dl1 < 16u && (dl1 & 6) == lb) {
                    float v = (dl1 < 8) ? ((dl1 & 1) ? a0[3] : a0[2])
                                        : ((dl1 & 1) ? a1[3] : a1[2]);
                    float l2 = fmaf(v, ITLG2E, negM);
                    Z1 -= ex2f(l2); P1 -= l2; C1c -= 1.f;
                }
            }
        }
        buf++; if (buf == 5) buf = 0;
    }

    // quad reduce (lanes sharing a row differ only in lane&3)
    #pragma unroll
    for (int o = 1; o <= 2; o <<= 1) {
        Z0 += __shfl_xor_sync(0xFFFFFFFFu, Z0, o);
        P0 += __shfl_xor_sync(0xFFFFFFFFu, P0, o);
        C0c += __shfl_xor_sync(0xFFFFFFFFu, C0c, o);
        Z1 += __shfl_xor_sync(0xFFFFFFFFu, Z1, o);
        P1 += __shfl_xor_sync(0xFFFFFFFFu, P1, o);
        C1c += __shfl_xor_sync(0xFFFFFFFFu, C1c, o);
    }
    if ((lane & 3) == 0) {
        int lr = wr * 16 + (lane >> 2);
        sZr[wc * 128 + lr] = Z0;  sPr[wc * 128 + lr] = P0;  sCr[wc * 128 + lr] = C0c;
        sZr[wc * 128 + lr + 8] = Z1;  sPr[wc * 128 + lr + 8] = P1;  sCr[wc * 128 + lr + 8] = C1c;
    }
    __syncthreads();
    if (tid < 128) {
        int gi = blockIdx.y * N_ITEMS + R0 + tid;
        g_Z[gi] = sZr[tid] + sZr[128 + tid];
        g_P[gi] = sPr[tid] + sPr[128 + tid];
        g_C[gi] = sCr[tid] + sCr[128 + tid];
    }
}

// ---------------- kernel 3: finalize loss ---------------------------------
__global__ __launch_bounds__(1024) void finalize_kernel(float* __restrict__ out, int out_size) {
    __shared__ float s[1024];
    int tid = threadIdx.x;
    float acc = 0.f;
    #pragma unroll
    for (int k = 0; k < 8; k++) {
        int r = tid + k * 1024;
        float Zv = g_Z[r] + g_Z[N_ITEMS + r];
        float Pv = (g_P[r] + g_P[N_ITEMS + r]) * LN2F;   // log2 -> ln
        float Cv = g_C[r] + g_C[N_ITEMS + r];
        float lnZ = lg2f(Zv + 1e-6f) * LN2F;
        acc += (Pv - Cv * lnZ) / (Cv + 1e-6f);
    }
    s[tid] = acc;
    __syncthreads();
    for (int o = 512; o; o >>= 1) {
        if (tid < o) s[tid] += s[tid + o];
        __syncthreads();
    }
    if (tid == 0) {
        float loss = -(s[0] / (float)N_ITEMS);
        for (int i = BATCHSZ; i < out_size; i++) out[i] = loss;
    }
}

// ---------------- launch ----------------------------------------------------
extern "C" void kernel_launch(void* const* d_in, const int* in_sizes, int n_in,
                              void* d_out, int out_size) {
    const int*   idx    = (const int*)d_in[0];
    const int*   labels = (const int*)d_in[1];
    const float* emb    = (const float*)d_in[2];
    const float* w      = (const float*)d_in[3];
    const float* b      = (const float*)d_in[4];
    float* out = (float*)d_out;

    const int SMEM = 16384 + 5 * 16384 + 5 * 512;   // 101120 B
    cudaFuncSetAttribute(supcon_kernel, cudaFuncAttributeMaxDynamicSharedMemorySize, SMEM);

    prep_kernel<<<N_ITEMS / 8 + BATCHSZ / 8, 256>>>(emb, idx, w, b, out);
    supcon_kernel<<<dim3(64, 2, 1), 512, SMEM>>>(labels);
    finalize_kernel<<<1, 1024>>>(out, out_size);
}

// round 8
// speedup vs baseline: 1.8311x; 1.0173x over previous
#include <cuda_runtime.h>
#include <cuda_fp16.h>
#include <cstdint>
#include <math.h>

#define N_ITEMS 8192
#define DIM     64
#define BATCHSZ 4096
#define LN2F    0.69314718055994531f
#define ITLG2E  20.609947181438156f   /* (1/0.07) * log2(e) */
#define NCH     32

// ---------------- device scratch (no allocations allowed) ----------------
__device__ uint32_t g_fh[N_ITEMS * 32];   // normalized rows, half2-packed [row][32]
__device__ float    g_Z[2 * N_ITEMS];
__device__ float    g_P[2 * N_ITEMS];     // log2-domain positive-logit sums
__device__ float    g_C[2 * N_ITEMS];

// ---------------- helpers --------------------------------------------------
static __device__ __forceinline__ uint32_t smem_u32(const void* p) {
    uint32_t a;
    asm("{ .reg .u64 t; cvta.to.shared.u64 t, %1; cvt.u32.u64 %0, t; }" : "=r"(a) : "l"(p));
    return a;
}
static __device__ __forceinline__ float ex2f(float x) {
    float y; asm("ex2.approx.ftz.f32 %0, %1;" : "=f"(y) : "f"(x)); return y;
}
static __device__ __forceinline__ float lg2f(float x) {
    float y; asm("lg2.approx.ftz.f32 %0, %1;" : "=f"(y) : "f"(x)); return y;
}
static __device__ __forceinline__ void cp16(uint32_t dst, const void* src) {
    asm volatile("cp.async.cg.shared.global [%0], [%1], 16;" :: "r"(dst), "l"(src));
}
#define CP_COMMIT() asm volatile("cp.async.commit_group;" ::: "memory")
static __device__ __forceinline__ void ldsm4(uint32_t* r, uint32_t addr) {
    asm volatile("ldmatrix.sync.aligned.m8n8.x4.shared.b16 {%0,%1,%2,%3}, [%4];"
                 : "=r"(r[0]), "=r"(r[1]), "=r"(r[2]), "=r"(r[3]) : "r"(addr));
}
static __device__ __forceinline__ void mma16816(float* d, const uint32_t* a,
                                                uint32_t b0, uint32_t b1) {
    asm volatile("mma.sync.aligned.m16n8k16.row.col.f32.f16.f16.f32 "
                 "{%0,%1,%2,%3}, {%4,%5,%6,%7}, {%8,%9}, {%0,%1,%2,%3};"
                 : "+f"(d[0]), "+f"(d[1]), "+f"(d[2]), "+f"(d[3])
                 : "r"(a[0]), "r"(a[1]), "r"(a[2]), "r"(a[3]), "r"(b0), "r"(b1));
}

// ---------------- kernel 1: fused normalize (fp16) + rating ---------------
__global__ __launch_bounds__(256) void prep_kernel(const float* __restrict__ emb,
                                                   const int* __restrict__ idx,
                                                   const float* __restrict__ w,
                                                   const float* __restrict__ bias,
                                                   float* __restrict__ out) {
    int bid  = blockIdx.x;
    int wid  = threadIdx.x >> 5;
    int lane = threadIdx.x & 31;
    if (bid < N_ITEMS / 8) {
        int row = bid * 8 + wid;
        float2 v = reinterpret_cast<const float2*>(emb + (size_t)row * DIM)[lane];
        float ss = v.x * v.x + v.y * v.y;
        #pragma unroll
        for (int o = 16; o; o >>= 1) ss += __shfl_xor_sync(0xFFFFFFFFu, ss, o);
        float inv = 1.0f / fmaxf(sqrtf(ss), 1e-12f);
        __half2 h = __floats2half2_rn(v.x * inv, v.y * inv);
        g_fh[row * 32 + lane] = *reinterpret_cast<uint32_t*>(&h);
    } else {
        int r = (bid - N_ITEMS / 8) * 8 + wid;
        int it = idx[r];
        float2 v  = reinterpret_cast<const float2*>(emb + (size_t)it * DIM)[lane];
        float2 ww = reinterpret_cast<const float2*>(w)[lane];
        float s = v.x * ww.x + v.y * ww.y;
        #pragma unroll
        for (int o = 16; o; o >>= 1) s += __shfl_xor_sync(0xFFFFFFFFu, s, o);
        if (lane == 0) out[r] = 1.0f / (1.0f + __expf(-(s + bias[0])));
    }
}

// ---------------- kernel 2: fp16 HMMA SupCon --------------------------------
// grid (64,2), 512 thr (16 warps). CTA: 128 rows x 4096 cols, 32 chunks of 128.
// Warp (wr=w&7, wc=w>>3): rows wr*16..+15, cols wc*64..+63 of the chunk.
// smem: A[0,16K), B ring 5 x 16K at 16K, labels ring 5 x 512B at 96K+16K.
// Swizzle: 16B chunk c of row r stored at c ^ (r&7).
#define BOFF 16384
#define LOFF (16384 + 5 * 16384)
static __device__ __forceinline__ void load_128x128(uint32_t sdst, const char* gsrc, int tid) {
    #pragma unroll
    for (int i = tid; i < 1024; i += 512) {
        uint32_t off = ((i >> 3) * 128) + ((i & 7) * 16);
        uint32_t sw  = off ^ ((off >> 3) & 0x70);
        cp16(sdst + sw, gsrc + off);
    }
}

__global__ __launch_bounds__(512, 1) void supcon_kernel(const int* __restrict__ labels) {
    extern __shared__ char dyn[];
    __shared__ float sZr[256], sPr[256], sCr[256];

    const int tid  = threadIdx.x;
    const int w    = tid >> 5;
    const int lane = tid & 31;
    const int wr   = w & 7;
    const int wc   = w >> 3;
    const int R0   = blockIdx.x * 128;
    const int Cb   = blockIdx.y * 4096;
    const uint32_t sbase = smem_u32(dyn);

    // ---- prologue: group0 = {A, B0, L0}; groups 1..3 = {Bk, Lk} ----
    load_128x128(sbase, (const char*)g_fh + (size_t)R0 * 128, tid);
    #pragma unroll
    for (int pf = 0; pf < 4; pf++) {
        load_128x128(sbase + BOFF + (uint32_t)pf * 16384,
                     (const char*)g_fh + (size_t)(Cb + pf * 128) * 128, tid);
        if (tid < 32) cp16(sbase + LOFF + pf * 512 + tid * 16,
                           (const char*)(labels + Cb + pf * 128) + tid * 16);
        CP_COMMIT();
    }
    asm volatile("cp.async.wait_group 3;" ::: "memory");
    __syncthreads();

    // ---- A fragments (chunk-invariant): rows wr*16..+15, K=64 ----
    uint32_t ah[4][4];
    {
        int arow = wr * 16 + (lane & 15);
        uint32_t rbase = sbase + (uint32_t)arow * 128;
        #pragma unroll
        for (int ks = 0; ks < 4; ks++) {
            uint32_t c = (uint32_t)(ks * 2 + (lane >> 4));
            ldsm4(ah[ks], rbase + ((c ^ (arow & 7)) << 4));
        }
    }

    const int grow0 = R0 + wr * 16 + (lane >> 2);
    const int grow1 = grow0 + 8;
    const float negM = -ITLG2E;
    const int rlab0 = labels[grow0];
    const int rlab1 = labels[grow1];
    const int lb = 2 * (lane & 3);
    const int bnoff = (((lane >> 4) & 1) << 3) + (lane & 7);
    const uint32_t bksel = (uint32_t)((lane >> 3) & 1);
    float Z0 = 0.f, P0 = 0.f, C0c = 0.f, Z1 = 0.f, P1 = 0.f, C1c = 0.f;

    int buf = 0;
    for (int t = 0; t < NCH; t++) {
        if (t > 0) {
            asm volatile("cp.async.wait_group 3;" ::: "memory");
            __syncthreads();     // chunk t ready; all warps done with chunk t-1
        }
        // prefetch chunk t+4 (wraps at tail; redundant loads harmless)
        {
            int pb = buf + 4; if (pb >= 5) pb -= 5;
            int pc = (t + 4) & 31;
            load_128x128(sbase + BOFF + (uint32_t)pb * 16384,
                         (const char*)g_fh + (size_t)(Cb + pc * 128) * 128, tid);
            if (tid < 32) cp16(sbase + LOFF + pb * 512 + tid * 16,
                               (const char*)(labels + Cb + pc * 128) + tid * 16);
            CP_COMMIT();
        }
        const uint32_t Bb = sbase + BOFF + (uint32_t)buf * 16384;
        const int2* labp = reinterpret_cast<const int2*>(dyn + LOFF + buf * 512);
        const int colbase = Cb + t * 128 + wc * 64;

        #pragma unroll
        for (int ntp = 0; ntp < 4; ntp++) {
            float a0[4] = {0.f, 0.f, 0.f, 0.f};
            float a1[4] = {0.f, 0.f, 0.f, 0.f};
            int n = wc * 64 + ntp * 16 + bnoff;
            uint32_t nb = Bb + (uint32_t)n * 128;
            #pragma unroll
            for (int ks = 0; ks < 4; ks++) {
                uint32_t c = (uint32_t)(ks * 2) + bksel;
                uint32_t bb[4];
                ldsm4(bb, nb + ((c ^ (n & 7)) << 4));
                mma16816(a0, ah[ks], bb[0], bb[1]);
                mma16816(a1, ah[ks], bb[2], bb[3]);
            }

            // epilogue for these 2 n-tiles (8 values)
            int2 jA = labp[wc * 32 + ntp * 8 + (lane & 3)];
            int2 jB = labp[wc * 32 + ntp * 8 + 4 + (lane & 3)];
            {
                float l2 = fmaf(a0[0], ITLG2E, negM);
                Z0 += ex2f(l2); if (jA.x == rlab0) { P0 += l2; C0c += 1.f; }
            }
            {
                float l2 = fmaf(a0[1], ITLG2E, negM);
                Z0 += ex2f(l2); if (jA.y == rlab0) { P0 += l2; C0c += 1.f; }
            }
            {
                float l2 = fmaf(a0[2], ITLG2E, negM);
                Z1 += ex2f(l2); if (jA.x == rlab1) { P1 += l2; C1c += 1.f; }
            }
            {
                float l2 = fmaf(a0[3], ITLG2E, negM);
                Z1 += ex2f(l2); if (jA.y == rlab1) { P1 += l2; C1c += 1.f; }
            }
            {
                float l2 = fmaf(a1[0], ITLG2E, negM);
                Z0 += ex2f(l2); if (jB.x == rlab0) { P0 += l2; C0c += 1.f; }
            }
            {
                float l2 = fmaf(a1[1], ITLG2E, negM);
                Z0 += ex2f(l2); if (jB.y == rlab0) { P0 += l2; C0c += 1.f; }
            }
            {
                float l2 = fmaf(a1[2], ITLG2E, negM);
                Z1 += ex2f(l2); if (jB.x == rlab1) { P1 += l2; C1c += 1.f; }
            }
            {
                float l2 = fmaf(a1[3], ITLG2E, negM);
                Z1 += ex2f(l2); if (jB.y == rlab1) { P1 += l2; C1c += 1.f; }
            }

            // diagonal fixup (warp-uniform guard, taken in at most one chunk/ntp)
            int dbase = (R0 + wr * 16) - (colbase + ntp * 16);
            if ((unsigned)(dbase + 15) < 31u) {
                int dl0 = dbase + (lane >> 2);
                if ((unsigned)dl0 < 16u && (dl0 & 6) == lb) {
                    float v = (dl0 < 8) ? ((dl0 & 1) ? a0[1] : a0[0])
                                        : ((dl0 & 1) ? a1[1] : a1[0]);
                    float l2 = fmaf(v, ITLG2E, negM);
                    Z0 -= ex2f(l2); P0 -= l2; C0c -= 1.f;
                }
                int dl1 = dbase + 8 + (lane >> 2);
                if ((unsigned)dl1 < 16u && (dl1 & 6) == lb) {
                    float v = (dl1 < 8) ? ((dl1 & 1) ? a0[3] : a0[2])
                                        : ((dl1 & 1) ? a1[3] : a1[2]);
                    float l2 = fmaf(v, ITLG2E, negM);
                    Z1 -= ex2f(l2); P1 -= l2; C1c -= 1.f;
                }
            }
        }
        buf++; if (buf == 5) buf = 0;
    }

    // quad reduce (lanes sharing a row differ only in lane&3)
    #pragma unroll
    for (int o = 1; o <= 2; o <<= 1) {
        Z0 += __shfl_xor_sync(0xFFFFFFFFu, Z0, o);
        P0 += __shfl_xor_sync(0xFFFFFFFFu, P0, o);
        C0c += __shfl_xor_sync(0xFFFFFFFFu, C0c, o);
        Z1 += __shfl_xor_sync(0xFFFFFFFFu, Z1, o);
        P1 += __shfl_xor_sync(0xFFFFFFFFu, P1, o);
        C1c += __shfl_xor_sync(0xFFFFFFFFu, C1c, o);
    }
    if ((lane & 3) == 0) {
        int lr = wr * 16 + (lane >> 2);
        sZr[wc * 128 + lr] = Z0;  sPr[wc * 128 + lr] = P0;  sCr[wc * 128 + lr] = C0c;
        sZr[wc * 128 + lr + 8] = Z1;  sPr[wc * 128 + lr + 8] = P1;  sCr[wc * 128 + lr + 8] = C1c;
    }
    __syncthreads();
    if (tid < 128) {
        int gi = blockIdx.y * N_ITEMS + R0 + tid;
        g_Z[gi] = sZr[tid] + sZr[128 + tid];
        g_P[gi] = sPr[tid] + sPr[128 + tid];
        g_C[gi] = sCr[tid] + sCr[128 + tid];
    }
}

// ---------------- kernel 3: finalize loss ---------------------------------
__global__ __launch_bounds__(1024) void finalize_kernel(float* __restrict__ out, int out_size) {
    __shared__ float s[1024];
    int tid = threadIdx.x;
    float acc = 0.f;
    #pragma unroll
    for (int k = 0; k < 8; k++) {
        int r = tid + k * 1024;
        float Zv = g_Z[r] + g_Z[N_ITEMS + r];
        float Pv = (g_P[r] + g_P[N_ITEMS + r]) * LN2F;   // log2 -> ln
        float Cv = g_C[r] + g_C[N_ITEMS + r];
        float lnZ = lg2f(Zv + 1e-6f) * LN2F;
        acc += (Pv - Cv * lnZ) / (Cv + 1e-6f);
    }
    s[tid] = acc;
    __syncthreads();
    for (int o = 512; o; o >>= 1) {
        if (tid < o) s[tid] += s[tid + o];
        __syncthreads();
    }
    if (tid == 0) {
        float loss = -(s[0] / (float)N_ITEMS);
        for (int i = BATCHSZ; i < out_size; i++) out[i] = loss;
    }
}

// ---------------- launch ----------------------------------------------------
extern "C" void kernel_launch(void* const* d_in, const int* in_sizes, int n_in,
                              void* d_out, int out_size) {
    const int*   idx    = (const int*)d_in[0];
    const int*   labels = (const int*)d_in[1];
    const float* emb    = (const float*)d_in[2];
    const float* w      = (const float*)d_in[3];
    const float* b      = (const float*)d_in[4];
    float* out = (float*)d_out;

    const int SMEM = 16384 + 5 * 16384 + 5 * 512;   // 101120 B
    cudaFuncSetAttribute(supcon_kernel, cudaFuncAttributeMaxDynamicSharedMemorySize, SMEM);

    prep_kernel<<<N_ITEMS / 8 + BATCHSZ / 8, 256>>>(emb, idx, w, b, out);
    supcon_kernel<<<dim3(64, 2, 1), 512, SMEM>>>(labels);
    finalize_kernel<<<1, 1024>>>(out, out_size);
}